// round 1
// baseline (speedup 1.0000x reference)
#include <cuda_runtime.h>
#include <cstdint>

#define NN 100000
#define NE 1600000

// Scratch (device globals — no runtime allocation allowed)
__device__ float g_S[(size_t)NN * 128];   // nodes @ W1[0:64]  + b1   (51.2 MB)
__device__ float g_R[(size_t)NN * 128];   // nodes @ W1[64:128]       (51.2 MB)
__device__ float g_deg[NN];               // degree, then 1/max(deg,1)

// ---------------------------------------------------------------------------
// Degree kernels
// ---------------------------------------------------------------------------
__global__ void zero_deg_kernel() {
    int i = blockIdx.x * blockDim.x + threadIdx.x;
    if (i < NN) g_deg[i] = 0.0f;
}

__global__ void deg_kernel(const int* __restrict__ recv) {
    int e = blockIdx.x * blockDim.x + threadIdx.x;
    if (e < NE) atomicAdd(&g_deg[recv[e]], 1.0f);
}

__global__ void invdeg_kernel() {
    int i = blockIdx.x * blockDim.x + threadIdx.x;
    if (i < NN) g_deg[i] = 1.0f / fmaxf(g_deg[i], 1.0f);
}

// ---------------------------------------------------------------------------
// Node-side GEMM: C[M x BN] = A[M x 64] @ B[64 x BN] (+ bias)
// BM=64, K=64 (full), 256 threads, thread tile 4 x TN.
// Used for S (BN=128, bias=b1), R (BN=128), node-term (BN=64, bias=bn).
// ---------------------------------------------------------------------------
template <int BN, int TN>
__global__ void __launch_bounds__(256) node_gemm_kernel(
    const float* __restrict__ A,        // [M,64]
    const float* __restrict__ B,        // rows stride ldb
    int ldb,
    const float* __restrict__ bias,     // [BN] or nullptr
    float* __restrict__ C,              // [M,BN]
    int M)
{
    extern __shared__ float sm[];
    float* sAT = sm;                    // [64 k][68 pad]  (transposed A tile)
    float* sB  = sm + 64 * 68;          // [64][BN]

    const int tid = threadIdx.x;
    const int n0  = blockIdx.x * 64;

    // Load A tile transposed: sAT[k][row]
#pragma unroll
    for (int j = 0; j < 4; j++) {
        int s   = tid + j * 256;        // 1024 float4 slots
        int row = s >> 4;
        int k0  = (s & 15) << 2;
        int gn  = n0 + row;
        float4 v = make_float4(0.f, 0.f, 0.f, 0.f);
        if (gn < M) v = *(const float4*)(A + (size_t)gn * 64 + k0);
        sAT[(k0 + 0) * 68 + row] = v.x;
        sAT[(k0 + 1) * 68 + row] = v.y;
        sAT[(k0 + 2) * 68 + row] = v.z;
        sAT[(k0 + 3) * 68 + row] = v.w;
    }
    // Load B tile
    constexpr int BV = BN / 4;
#pragma unroll
    for (int j = 0; j < (64 * BV) / 256; j++) {
        int s  = tid + j * 256;
        int r  = s / BV;
        int c4 = (s % BV) * 4;
        *(float4*)(sB + r * BN + c4) = *(const float4*)(B + (size_t)r * ldb + c4);
    }
    __syncthreads();

    const int ty = tid >> 4;            // 0..15 -> node rows ty*4..+3
    const int tx = tid & 15;            // 0..15 -> cols tx*TN..

    float acc[4][TN];
#pragma unroll
    for (int m = 0; m < 4; m++)
#pragma unroll
        for (int n = 0; n < TN; n++) acc[m][n] = 0.f;

#pragma unroll 16
    for (int k = 0; k < 64; k++) {
        float4 a4 = *(const float4*)(sAT + k * 68 + ty * 4);
        float av[4] = {a4.x, a4.y, a4.z, a4.w};
        float bv[TN];
#pragma unroll
        for (int n4 = 0; n4 < TN / 4; n4++) {
            float4 b4 = *(const float4*)(sB + k * BN + tx * TN + n4 * 4);
            bv[n4 * 4 + 0] = b4.x; bv[n4 * 4 + 1] = b4.y;
            bv[n4 * 4 + 2] = b4.z; bv[n4 * 4 + 3] = b4.w;
        }
#pragma unroll
        for (int m = 0; m < 4; m++)
#pragma unroll
            for (int n = 0; n < TN; n++) acc[m][n] += av[m] * bv[n];
    }

    float bb[TN];
#pragma unroll
    for (int n = 0; n < TN; n++) bb[n] = bias ? bias[tx * TN + n] : 0.f;

#pragma unroll
    for (int m = 0; m < 4; m++) {
        int gn = n0 + ty * 4 + m;
        if (gn < M) {
#pragma unroll
            for (int n4 = 0; n4 < TN / 4; n4++) {
                float4 v;
                v.x = acc[m][n4 * 4 + 0] + bb[n4 * 4 + 0];
                v.y = acc[m][n4 * 4 + 1] + bb[n4 * 4 + 1];
                v.z = acc[m][n4 * 4 + 2] + bb[n4 * 4 + 2];
                v.w = acc[m][n4 * 4 + 3] + bb[n4 * 4 + 3];
                *(float4*)(C + (size_t)gn * BN + tx * TN + n4 * 4) = v;
            }
        }
    }
}

// ---------------------------------------------------------------------------
// Fused edge kernel: per tile of 128 edges
//   GEMM1: t = edge_feats[128x32] @ W1c[32x128]
//   h = relu(t + S[send] + R[recv])               (b1 folded into S)
//   GEMM2: m = h[128x128] @ W2[128x64] + b2
//   scatter: out[recv] += m * invdeg[recv]        (red.global.add.v4.f32)
// ---------------------------------------------------------------------------
__global__ void __launch_bounds__(256) edge_kernel(
    const float* __restrict__ edges,       // [NE,32]
    const int*   __restrict__ senders,
    const int*   __restrict__ receivers,
    const float* __restrict__ W1,          // [160,128]
    const float* __restrict__ W2,          // [128,64]
    const float* __restrict__ b2,          // [64]
    float*       __restrict__ out)         // [NN,64]
{
    extern __shared__ float sm[];
    float* sW1c = sm;                      // 32*128 = 4096 floats
    float* sW2  = sm + 4096;               // 128*64 = 8192 floats
    float* sE   = sm + 4096 + 8192;        // [32 i][132 pad]   (transposed edges)
    float* sH   = sE + 32 * 132;           // [128 k][132 pad]  (h transposed)
    int*   sSend = (int*)(sH + 128 * 132); // [128]
    int*   sRecv = sSend + 128;            // [128]

    const int tid = threadIdx.x;
    const int e0  = blockIdx.x * 128;

    if (tid < 128) sSend[tid] = senders[e0 + tid];
    else           sRecv[tid - 128] = receivers[e0 + tid - 128];

    // W1c = W1 rows 128..159 (linear copy)
#pragma unroll
    for (int j = 0; j < 4; j++) {
        int s = tid + j * 256;
        *(float4*)(sW1c + s * 4) = *(const float4*)(W1 + 128 * 128 + s * 4);
    }
    // W2 (linear copy)
#pragma unroll
    for (int j = 0; j < 8; j++) {
        int s = tid + j * 256;
        *(float4*)(sW2 + s * 4) = *(const float4*)(W2 + s * 4);
    }
    // edge feats, transposed to sE[i][e]
#pragma unroll
    for (int j = 0; j < 4; j++) {
        int s  = tid + j * 256;            // 1024 float4 slots
        int e  = s >> 3;
        int i0 = (s & 7) * 4;
        float4 v = *(const float4*)(edges + (size_t)(e0 + e) * 32 + i0);
        sE[(i0 + 0) * 132 + e] = v.x;
        sE[(i0 + 1) * 132 + e] = v.y;
        sE[(i0 + 2) * 132 + e] = v.z;
        sE[(i0 + 3) * 132 + e] = v.w;
    }
    __syncthreads();

    const int ty = tid >> 4;               // 0..15
    const int tx = tid & 15;               // 0..15
    const int eb = ty * 8;                 // edge base
    const int kb = tx * 8;                 // hidden base

    // ---- GEMM1: acc[e][k] = sum_i E[e][i] * W1c[i][k] ----
    float acc[8][8];
#pragma unroll
    for (int e = 0; e < 8; e++)
#pragma unroll
        for (int k = 0; k < 8; k++) acc[e][k] = 0.f;

#pragma unroll 8
    for (int i = 0; i < 32; i++) {
        float4 a0 = *(const float4*)(sE + i * 132 + eb);
        float4 a1 = *(const float4*)(sE + i * 132 + eb + 4);
        float4 w0 = *(const float4*)(sW1c + i * 128 + kb);
        float4 w1 = *(const float4*)(sW1c + i * 128 + kb + 4);
        float av[8] = {a0.x, a0.y, a0.z, a0.w, a1.x, a1.y, a1.z, a1.w};
        float wv[8] = {w0.x, w0.y, w0.z, w0.w, w1.x, w1.y, w1.z, w1.w};
#pragma unroll
        for (int e = 0; e < 8; e++)
#pragma unroll
            for (int k = 0; k < 8; k++) acc[e][k] += av[e] * wv[k];
    }

    // ---- epilogue 1: h = relu(acc + S[send] + R[recv]) ----
#pragma unroll
    for (int e = 0; e < 8; e++) {
        int es = sSend[eb + e];
        int er = sRecv[eb + e];
        float4 s0 = *(const float4*)(g_S + (size_t)es * 128 + kb);
        float4 s1 = *(const float4*)(g_S + (size_t)es * 128 + kb + 4);
        float4 r0 = *(const float4*)(g_R + (size_t)er * 128 + kb);
        float4 r1 = *(const float4*)(g_R + (size_t)er * 128 + kb + 4);
        acc[e][0] = fmaxf(acc[e][0] + s0.x + r0.x, 0.f);
        acc[e][1] = fmaxf(acc[e][1] + s0.y + r0.y, 0.f);
        acc[e][2] = fmaxf(acc[e][2] + s0.z + r0.z, 0.f);
        acc[e][3] = fmaxf(acc[e][3] + s0.w + r0.w, 0.f);
        acc[e][4] = fmaxf(acc[e][4] + s1.x + r1.x, 0.f);
        acc[e][5] = fmaxf(acc[e][5] + s1.y + r1.y, 0.f);
        acc[e][6] = fmaxf(acc[e][6] + s1.z + r1.z, 0.f);
        acc[e][7] = fmaxf(acc[e][7] + s1.w + r1.w, 0.f);
    }

    // store h transposed: sH[k][e], float4 along e
#pragma unroll
    for (int j = 0; j < 8; j++) {
        float4 v0 = make_float4(acc[0][j], acc[1][j], acc[2][j], acc[3][j]);
        float4 v1 = make_float4(acc[4][j], acc[5][j], acc[6][j], acc[7][j]);
        *(float4*)(sH + (kb + j) * 132 + eb)     = v0;
        *(float4*)(sH + (kb + j) * 132 + eb + 4) = v1;
    }
    __syncthreads();

    // ---- GEMM2: m[e][n] = sum_k h[k][e] * W2[k][n] ----
    const int nb = tx * 4;                 // out-col base
    float acc2[8][4];
#pragma unroll
    for (int e = 0; e < 8; e++)
#pragma unroll
        for (int n = 0; n < 4; n++) acc2[e][n] = 0.f;

#pragma unroll 8
    for (int k = 0; k < 128; k++) {
        float4 h0 = *(const float4*)(sH + k * 132 + eb);
        float4 h1 = *(const float4*)(sH + k * 132 + eb + 4);
        float4 w  = *(const float4*)(sW2 + k * 64 + nb);
        float hv[8] = {h0.x, h0.y, h0.z, h0.w, h1.x, h1.y, h1.z, h1.w};
#pragma unroll
        for (int e = 0; e < 8; e++) {
            acc2[e][0] += hv[e] * w.x;
            acc2[e][1] += hv[e] * w.y;
            acc2[e][2] += hv[e] * w.z;
            acc2[e][3] += hv[e] * w.w;
        }
    }

    // ---- epilogue 2: vector-atomic scatter of m * invdeg ----
    float4 b2v = *(const float4*)(b2 + nb);
#pragma unroll
    for (int e = 0; e < 8; e++) {
        int er = sRecv[eb + e];
        float invd = g_deg[er];            // already inverted
        float x = (acc2[e][0] + b2v.x) * invd;
        float y = (acc2[e][1] + b2v.y) * invd;
        float z = (acc2[e][2] + b2v.z) * invd;
        float w = (acc2[e][3] + b2v.w) * invd;
        float* p = out + (size_t)er * 64 + nb;
        asm volatile("red.global.add.v4.f32 [%0], {%1,%2,%3,%4};"
                     :: "l"(p), "f"(x), "f"(y), "f"(z), "f"(w) : "memory");
    }
}

// ---------------------------------------------------------------------------
// Launch
// ---------------------------------------------------------------------------
extern "C" void kernel_launch(void* const* d_in, const int* in_sizes, int n_in,
                              void* d_out, int out_size)
{
    const float* nodes     = (const float*)d_in[0];
    const float* edges     = (const float*)d_in[1];
    const int*   senders   = (const int*)d_in[2];
    const int*   receivers = (const int*)d_in[3];
    const float* W1        = (const float*)d_in[4];  // [160,128]
    const float* b1        = (const float*)d_in[5];
    const float* W2        = (const float*)d_in[6];  // [128,64]
    const float* b2        = (const float*)d_in[7];
    const float* Wn        = (const float*)d_in[8];  // [64,64]
    const float* bn        = (const float*)d_in[9];
    float* out = (float*)d_out;

    float *pS = nullptr, *pR = nullptr;
    cudaGetSymbolAddress((void**)&pS, g_S);
    cudaGetSymbolAddress((void**)&pR, g_R);

    const size_t sm_gemm128 = (64 * 68 + 64 * 128) * sizeof(float);   // ~50 KB
    const size_t sm_gemm64  = (64 * 68 + 64 * 64) * sizeof(float);
    const size_t sm_edge    = (4096 + 8192 + 32 * 132 + 128 * 132) * sizeof(float)
                              + 256 * sizeof(int);                    // ~135 KB

    cudaFuncSetAttribute(node_gemm_kernel<128, 8>,
                         cudaFuncAttributeMaxDynamicSharedMemorySize, (int)sm_gemm128);
    cudaFuncSetAttribute(edge_kernel,
                         cudaFuncAttributeMaxDynamicSharedMemorySize, (int)sm_edge);

    // degree -> invdeg
    zero_deg_kernel<<<(NN + 255) / 256, 256>>>();
    deg_kernel<<<(NE + 255) / 256, 256>>>(receivers);
    invdeg_kernel<<<(NN + 255) / 256, 256>>>();

    // node-side precompute
    int gnodes = (NN + 63) / 64;
    node_gemm_kernel<128, 8><<<gnodes, 256, sm_gemm128>>>(nodes, W1, 128, b1, pS, NN);
    node_gemm_kernel<128, 8><<<gnodes, 256, sm_gemm128>>>(nodes, W1 + 64 * 128, 128, nullptr, pR, NN);
    node_gemm_kernel<64, 4><<<gnodes, 256, sm_gemm64>>>(nodes, Wn, 64, bn, out, NN);

    // fused edge MLP + scatter
    edge_kernel<<<NE / 128, 256, sm_edge>>>(edges, senders, receivers, W1, W2, b2, out);
}

// round 2
// speedup vs baseline: 1.1460x; 1.1460x over previous
#include <cuda_runtime.h>
#include <cstdint>

#define NN 100000
#define NE 1600000

typedef unsigned long long ull;

// Scratch (device globals — no runtime allocation allowed)
__device__ float g_SR[(size_t)NN * 256];  // [n][0:128]=nodes@W1a+b1, [128:256]=nodes@W1b
__device__ float g_deg[NN];               // degree, then 1/max(deg,1)

// ---------------------------------------------------------------------------
// packed fp32x2 helpers
// ---------------------------------------------------------------------------
__device__ __forceinline__ ull dup2(float x) {
    ull r; asm("mov.b64 %0,{%1,%1};" : "=l"(r) : "f"(x)); return r;
}
__device__ __forceinline__ float2 up2(ull v) {
    float2 r; asm("mov.b64 {%0,%1},%2;" : "=f"(r.x), "=f"(r.y) : "l"(v)); return r;
}
__device__ __forceinline__ ull fma2(ull a, ull b, ull c) {
    ull d; asm("fma.rn.f32x2 %0,%1,%2,%3;" : "=l"(d) : "l"(a), "l"(b), "l"(c)); return d;
}

// ---------------------------------------------------------------------------
// Degree kernels
// ---------------------------------------------------------------------------
__global__ void zero_deg_kernel() {
    int i = blockIdx.x * blockDim.x + threadIdx.x;
    if (i < NN) g_deg[i] = 0.0f;
}
__global__ void deg_kernel(const int* __restrict__ recv) {
    int e = blockIdx.x * blockDim.x + threadIdx.x;
    if (e < NE) atomicAdd(&g_deg[recv[e]], 1.0f);
}
__global__ void invdeg_kernel() {
    int i = blockIdx.x * blockDim.x + threadIdx.x;
    if (i < NN) g_deg[i] = 1.0f / fmaxf(g_deg[i], 1.0f);
}

// ---------------------------------------------------------------------------
// Fused S|R precompute: g_SR[M,256] = nodes[M,64] @ [W1a | W1b][64,256], b1 on S half
// 256 threads, thread tile 4m x (4q x 4n), packed f32x2 along n.
// ---------------------------------------------------------------------------
__global__ void __launch_bounds__(256) sr_gemm_kernel(
    const float* __restrict__ A,   // nodes [M,64]
    const float* __restrict__ W1,  // [160,128]
    const float* __restrict__ b1,  // [128]
    int M)
{
    extern __shared__ float sm[];
    float* sAT = sm;               // [64 k][68] transposed A tile
    float* sB  = sm + 64 * 68;     // [64 k][256 n]

    const int tid = threadIdx.x;
    const int n0  = blockIdx.x * 64;

    // A tile transposed
#pragma unroll
    for (int j = 0; j < 4; j++) {
        int s   = tid + j * 256;
        int row = s >> 4;
        int k0  = (s & 15) << 2;
        int gn  = n0 + row;
        float4 v = make_float4(0.f, 0.f, 0.f, 0.f);
        if (gn < M) v = *(const float4*)(A + (size_t)gn * 64 + k0);
        sAT[(k0 + 0) * 68 + row] = v.x;
        sAT[(k0 + 1) * 68 + row] = v.y;
        sAT[(k0 + 2) * 68 + row] = v.z;
        sAT[(k0 + 3) * 68 + row] = v.w;
    }
    // B tile: cols 0..127 from W1 rows 0..63, cols 128..255 from W1 rows 64..127
#pragma unroll
    for (int j = 0; j < 16; j++) {
        int s  = tid + j * 256;
        int r  = s >> 6;
        int c4 = (s & 63) * 4;
        const float* src = (c4 < 128) ? (W1 + (size_t)r * 128 + c4)
                                      : (W1 + (size_t)(64 + r) * 128 + (c4 - 128));
        *(float4*)(sB + r * 256 + c4) = *(const float4*)src;
    }
    __syncthreads();

    const int ty = tid >> 4;       // 0..15 -> rows ty*4..+3
    const int tx = tid & 15;       // n = q*64 + tx*4 + {0..3}

    ull acc[4][4][2];
#pragma unroll
    for (int m = 0; m < 4; m++)
#pragma unroll
        for (int q = 0; q < 4; q++) { acc[m][q][0] = 0ull; acc[m][q][1] = 0ull; }

#pragma unroll 8
    for (int k = 0; k < 64; k++) {
        float4 a = *(const float4*)(sAT + k * 68 + ty * 4);
        ull aa[4] = {dup2(a.x), dup2(a.y), dup2(a.z), dup2(a.w)};
#pragma unroll
        for (int q = 0; q < 4; q++) {
            ulonglong2 b = *(const ulonglong2*)(sB + k * 256 + q * 64 + tx * 4);
#pragma unroll
            for (int m = 0; m < 4; m++) {
                acc[m][q][0] = fma2(aa[m], b.x, acc[m][q][0]);
                acc[m][q][1] = fma2(aa[m], b.y, acc[m][q][1]);
            }
        }
    }

    // bias per q-chunk (only q<2 carries b1; R half gets 0)
    float4 bq[4];
#pragma unroll
    for (int q = 0; q < 4; q++) {
        if (q < 2) bq[q] = *(const float4*)(b1 + q * 64 + tx * 4);
        else       bq[q] = make_float4(0.f, 0.f, 0.f, 0.f);
    }

#pragma unroll
    for (int m = 0; m < 4; m++) {
        int gn = n0 + ty * 4 + m;
        if (gn < M) {
#pragma unroll
            for (int q = 0; q < 4; q++) {
                float2 u0 = up2(acc[m][q][0]);
                float2 u1 = up2(acc[m][q][1]);
                float4 v = make_float4(u0.x + bq[q].x, u0.y + bq[q].y,
                                       u1.x + bq[q].z, u1.y + bq[q].w);
                *(float4*)(g_SR + (size_t)gn * 256 + q * 64 + tx * 4) = v;
            }
        }
    }
}

// ---------------------------------------------------------------------------
// Node residual GEMM (scalar, small): out[M,64] = nodes @ Wn + bn
// ---------------------------------------------------------------------------
__global__ void __launch_bounds__(256) node_gemm_small(
    const float* __restrict__ A, const float* __restrict__ B,
    const float* __restrict__ bias, float* __restrict__ C, int M)
{
    extern __shared__ float sm[];
    float* sAT = sm;               // [64][68]
    float* sB  = sm + 64 * 68;     // [64][64]

    const int tid = threadIdx.x;
    const int n0  = blockIdx.x * 64;

#pragma unroll
    for (int j = 0; j < 4; j++) {
        int s   = tid + j * 256;
        int row = s >> 4;
        int k0  = (s & 15) << 2;
        int gn  = n0 + row;
        float4 v = make_float4(0.f, 0.f, 0.f, 0.f);
        if (gn < M) v = *(const float4*)(A + (size_t)gn * 64 + k0);
        sAT[(k0 + 0) * 68 + row] = v.x;
        sAT[(k0 + 1) * 68 + row] = v.y;
        sAT[(k0 + 2) * 68 + row] = v.z;
        sAT[(k0 + 3) * 68 + row] = v.w;
    }
#pragma unroll
    for (int j = 0; j < 4; j++) {
        int s = tid + j * 256;
        ((float4*)sB)[s] = ((const float4*)B)[s];
    }
    __syncthreads();

    const int ty = tid >> 4, tx = tid & 15;
    ull acc[4][2];
#pragma unroll
    for (int m = 0; m < 4; m++) { acc[m][0] = 0ull; acc[m][1] = 0ull; }

#pragma unroll 8
    for (int k = 0; k < 64; k++) {
        float4 a = *(const float4*)(sAT + k * 68 + ty * 4);
        ulonglong2 b = *(const ulonglong2*)(sB + k * 64 + tx * 4);
        ull aa[4] = {dup2(a.x), dup2(a.y), dup2(a.z), dup2(a.w)};
#pragma unroll
        for (int m = 0; m < 4; m++) {
            acc[m][0] = fma2(aa[m], b.x, acc[m][0]);
            acc[m][1] = fma2(aa[m], b.y, acc[m][1]);
        }
    }

    float4 bb = *(const float4*)(bias + tx * 4);
#pragma unroll
    for (int m = 0; m < 4; m++) {
        int gn = n0 + ty * 4 + m;
        if (gn < M) {
            float2 u0 = up2(acc[m][0]);
            float2 u1 = up2(acc[m][1]);
            float4 v = make_float4(u0.x + bb.x, u0.y + bb.y, u1.x + bb.z, u1.y + bb.w);
            *(float4*)(C + (size_t)gn * 64 + tx * 4) = v;
        }
    }
}

// ---------------------------------------------------------------------------
// Fused edge kernel: 256 edges per block, 256 threads, packed f32x2
// ---------------------------------------------------------------------------
__global__ void __launch_bounds__(256) edge_kernel(
    const float* __restrict__ edges,       // [NE,32]
    const int*   __restrict__ senders,
    const int*   __restrict__ receivers,
    const float* __restrict__ W1,          // [160,128]
    const float* __restrict__ W2,          // [128,64]
    const float* __restrict__ b2,          // [64]
    float*       __restrict__ out)         // [NN,64]
{
    extern __shared__ float sm[];
    float* sW1c = sm;                      // 4096  (W1 rows 128..159)
    float* sW2  = sm + 4096;               // 8192
    float* sE   = sm + 12288;              // [32 i][260]  transposed edge feats
    float* sH   = sm + 12288 + 8320;       // [128 k][256 e] swizzled granules
    int*   sSend = (int*)(sH + 128 * 256); // [256]
    int*   sRecv = sSend + 256;            // [256]

    const int tid = threadIdx.x;
    const int e0  = blockIdx.x * 256;

    sSend[tid] = senders[e0 + tid];
    sRecv[tid] = receivers[e0 + tid];

#pragma unroll
    for (int j = 0; j < 4; j++) {
        int s = tid + j * 256;
        ((float4*)sW1c)[s] = ((const float4*)(W1 + 128 * 128))[s];
    }
#pragma unroll
    for (int j = 0; j < 8; j++) {
        int s = tid + j * 256;
        ((float4*)sW2)[s] = ((const float4*)W2)[s];
    }
#pragma unroll
    for (int j = 0; j < 8; j++) {
        int s  = tid + j * 256;
        int e  = s >> 3;
        int i0 = (s & 7) * 4;
        float4 v = *(const float4*)(edges + (size_t)(e0 + e) * 32 + i0);
        sE[(i0 + 0) * 260 + e] = v.x;
        sE[(i0 + 1) * 260 + e] = v.y;
        sE[(i0 + 2) * 260 + e] = v.z;
        sE[(i0 + 3) * 260 + e] = v.w;
    }
    __syncthreads();

    const int ty = tid >> 4;               // 0..15
    const int tx = tid & 15;               // 0..15
    const int kA = tx * 4;                 // k chunks: {kA..kA+3} and {64+kA..+3}
    float4* H4 = (float4*)sH;

    // ================= GEMM1 (two passes over e-halves) =================
#pragma unroll
    for (int p = 0; p < 2; p++) {
        const int ebl = p * 128 + ty * 8;
        ull acc[8][4];
#pragma unroll
        for (int e = 0; e < 8; e++)
#pragma unroll
            for (int c = 0; c < 4; c++) acc[e][c] = 0ull;

#pragma unroll 8
        for (int i = 0; i < 32; i++) {
            float4 a0 = *(const float4*)(sE + i * 260 + ebl);
            float4 a1 = *(const float4*)(sE + i * 260 + ebl + 4);
            ulonglong2 w0 = *(const ulonglong2*)(sW1c + i * 128 + kA);
            ulonglong2 w1 = *(const ulonglong2*)(sW1c + i * 128 + 64 + kA);
            float av[8] = {a0.x, a0.y, a0.z, a0.w, a1.x, a1.y, a1.z, a1.w};
#pragma unroll
            for (int e = 0; e < 8; e++) {
                ull aa = dup2(av[e]);
                acc[e][0] = fma2(aa, w0.x, acc[e][0]);
                acc[e][1] = fma2(aa, w0.y, acc[e][1]);
                acc[e][2] = fma2(aa, w1.x, acc[e][2]);
                acc[e][3] = fma2(aa, w1.y, acc[e][3]);
            }
        }

        // epilogue: h = relu(acc + S[send] + R[recv]); b1 folded into S
        float hbuf[8][8];
#pragma unroll
        for (int e = 0; e < 8; e++) {
            int ge = ebl + e;
            int es = sSend[ge];
            int er = sRecv[ge];
            const float* Sp = g_SR + (size_t)es * 256;
            const float* Rp = g_SR + (size_t)er * 256 + 128;
            float4 s0 = *(const float4*)(Sp + kA);
            float4 s1 = *(const float4*)(Sp + 64 + kA);
            float4 r0 = *(const float4*)(Rp + kA);
            float4 r1 = *(const float4*)(Rp + 64 + kA);
            float2 u;
            u = up2(acc[e][0]);
            hbuf[e][0] = fmaxf(u.x + s0.x + r0.x, 0.f);
            hbuf[e][1] = fmaxf(u.y + s0.y + r0.y, 0.f);
            u = up2(acc[e][1]);
            hbuf[e][2] = fmaxf(u.x + s0.z + r0.z, 0.f);
            hbuf[e][3] = fmaxf(u.y + s0.w + r0.w, 0.f);
            u = up2(acc[e][2]);
            hbuf[e][4] = fmaxf(u.x + s1.x + r1.x, 0.f);
            hbuf[e][5] = fmaxf(u.y + s1.y + r1.y, 0.f);
            u = up2(acc[e][3]);
            hbuf[e][6] = fmaxf(u.x + s1.z + r1.z, 0.f);
            hbuf[e][7] = fmaxf(u.y + s1.w + r1.w, 0.f);
        }

        // store h transposed into sH with XOR granule swizzle
        const int c0 = ebl >> 2;
#pragma unroll
        for (int j = 0; j < 4; j++) {
            int k0  = kA + j;
            int sw0 = (k0 >> 3) & 7;
            H4[(k0 << 6) + (c0 ^ sw0)]       = make_float4(hbuf[0][j], hbuf[1][j], hbuf[2][j], hbuf[3][j]);
            H4[(k0 << 6) + ((c0 + 1) ^ sw0)] = make_float4(hbuf[4][j], hbuf[5][j], hbuf[6][j], hbuf[7][j]);
            int k1  = 64 + kA + j;
            int sw1 = (k1 >> 3) & 7;
            H4[(k1 << 6) + (c0 ^ sw1)]       = make_float4(hbuf[0][4 + j], hbuf[1][4 + j], hbuf[2][4 + j], hbuf[3][4 + j]);
            H4[(k1 << 6) + ((c0 + 1) ^ sw1)] = make_float4(hbuf[4][4 + j], hbuf[5][4 + j], hbuf[6][4 + j], hbuf[7][4 + j]);
        }
    }
    __syncthreads();

    // ================= GEMM2: m[256e x 64n] = h @ W2 =================
    const int ty2 = tid >> 3;              // 0..31 -> e-rows ty2*8..
    const int tx2 = tid & 7;               // 0..7  -> n cols tx2*8..
    const int eb2 = ty2 * 8;
    const int nb  = tx2 * 8;
    const int c2  = ty2 * 2;

    ull acc2[4][8];
#pragma unroll
    for (int e2 = 0; e2 < 4; e2++)
#pragma unroll
        for (int n = 0; n < 8; n++) acc2[e2][n] = 0ull;

#pragma unroll 4
    for (int k = 0; k < 128; k++) {
        int sw = (k >> 3) & 7;
        ulonglong2 h01 = *(const ulonglong2*)&H4[(k << 6) + (c2 ^ sw)];
        ulonglong2 h23 = *(const ulonglong2*)&H4[(k << 6) + ((c2 + 1) ^ sw)];
        float4 w0 = *(const float4*)(sW2 + k * 64 + nb);
        float4 w1 = *(const float4*)(sW2 + k * 64 + nb + 4);
        float wv[8] = {w0.x, w0.y, w0.z, w0.w, w1.x, w1.y, w1.z, w1.w};
#pragma unroll
        for (int n = 0; n < 8; n++) {
            ull ww = dup2(wv[n]);
            acc2[0][n] = fma2(h01.x, ww, acc2[0][n]);
            acc2[1][n] = fma2(h01.y, ww, acc2[1][n]);
            acc2[2][n] = fma2(h23.x, ww, acc2[2][n]);
            acc2[3][n] = fma2(h23.y, ww, acc2[3][n]);
        }
    }

    // epilogue 2: scatter (m + b2) * invdeg via vector reds
    float4 b2a = *(const float4*)(b2 + nb);
    float4 b2b = *(const float4*)(b2 + nb + 4);
    float bnv[8] = {b2a.x, b2a.y, b2a.z, b2a.w, b2b.x, b2b.y, b2b.z, b2b.w};

#pragma unroll
    for (int e2 = 0; e2 < 4; e2++) {
        float2 mv[8];
#pragma unroll
        for (int n = 0; n < 8; n++) mv[n] = up2(acc2[e2][n]);
#pragma unroll
        for (int h = 0; h < 2; h++) {
            int ge = eb2 + e2 * 2 + h;
            int er = sRecv[ge];
            float invd = g_deg[er];
            float v0 = ((h ? mv[0].y : mv[0].x) + bnv[0]) * invd;
            float v1 = ((h ? mv[1].y : mv[1].x) + bnv[1]) * invd;
            float v2 = ((h ? mv[2].y : mv[2].x) + bnv[2]) * invd;
            float v3 = ((h ? mv[3].y : mv[3].x) + bnv[3]) * invd;
            float v4 = ((h ? mv[4].y : mv[4].x) + bnv[4]) * invd;
            float v5 = ((h ? mv[5].y : mv[5].x) + bnv[5]) * invd;
            float v6 = ((h ? mv[6].y : mv[6].x) + bnv[6]) * invd;
            float v7 = ((h ? mv[7].y : mv[7].x) + bnv[7]) * invd;
            float* p = out + (size_t)er * 64 + nb;
            asm volatile("red.global.add.v4.f32 [%0], {%1,%2,%3,%4};"
                         :: "l"(p), "f"(v0), "f"(v1), "f"(v2), "f"(v3) : "memory");
            asm volatile("red.global.add.v4.f32 [%0], {%1,%2,%3,%4};"
                         :: "l"(p + 4), "f"(v4), "f"(v5), "f"(v6), "f"(v7) : "memory");
        }
    }
}

// ---------------------------------------------------------------------------
// Launch
// ---------------------------------------------------------------------------
extern "C" void kernel_launch(void* const* d_in, const int* in_sizes, int n_in,
                              void* d_out, int out_size)
{
    const float* nodes     = (const float*)d_in[0];
    const float* edges     = (const float*)d_in[1];
    const int*   senders   = (const int*)d_in[2];
    const int*   receivers = (const int*)d_in[3];
    const float* W1        = (const float*)d_in[4];  // [160,128]
    const float* b1        = (const float*)d_in[5];
    const float* W2        = (const float*)d_in[6];  // [128,64]
    const float* b2        = (const float*)d_in[7];
    const float* Wn        = (const float*)d_in[8];  // [64,64]
    const float* bn        = (const float*)d_in[9];
    float* out = (float*)d_out;

    const size_t sm_sr    = (64 * 68 + 64 * 256) * sizeof(float);           // ~81 KB
    const size_t sm_small = (64 * 68 + 64 * 64) * sizeof(float);            // ~33 KB
    const size_t sm_edge  = (4096 + 8192 + 32 * 260 + 128 * 256) * sizeof(float)
                            + 512 * sizeof(int);                            // ~210.5 KB

    cudaFuncSetAttribute(sr_gemm_kernel,
                         cudaFuncAttributeMaxDynamicSharedMemorySize, (int)sm_sr);
    cudaFuncSetAttribute(edge_kernel,
                         cudaFuncAttributeMaxDynamicSharedMemorySize, (int)sm_edge);

    // degree -> invdeg
    zero_deg_kernel<<<(NN + 255) / 256, 256>>>();
    deg_kernel<<<(NE + 255) / 256, 256>>>(receivers);
    invdeg_kernel<<<(NN + 255) / 256, 256>>>();

    // node-side precompute
    int gnodes = (NN + 63) / 64;
    sr_gemm_kernel<<<gnodes, 256, sm_sr>>>(nodes, W1, b1, NN);
    node_gemm_small<<<gnodes, 256, sm_small>>>(nodes, Wn, bn, out, NN);

    // fused edge MLP + scatter
    edge_kernel<<<NE / 256, 256, sm_edge>>>(edges, senders, receivers, W1, W2, b2, out);
}